// round 3
// baseline (speedup 1.0000x reference)
#include <cuda_runtime.h>

#define BS   16
#define NN   1024
#define FIN  128
#define FOUT 64
#define NH   4
#define NEG  0.2f
#define NW   (NN/32)   // 32 adj words per row

typedef unsigned long long u64;

// ---- scratch ----
__device__ float    g_hp[(size_t)BS*NH*NN*FOUT];   // 16 MB
__device__ unsigned g_adj[(size_t)BS*NN*NW];       // 2 MB
__device__ float    g_src [BS*NH*NN];
__device__ float    g_Es  [BS*NH*NN];
__device__ float    g_E2s [BS*NH*NN];
__device__ float    g_dstv[BS*NH*NN];
__device__ float    g_Fd  [BS*NH*NN];
__device__ float    g_F2d [BS*NH*NN];

#define FMA2(acc, a, b) asm("fma.rn.f32x2 %0, %1, %2, %0;" : "+l"(acc) : "l"(a), "l"(b))
#define PACK2(dst, f)   asm("mov.b64 %0, {%1, %1};" : "=l"(dst) : "r"(__float_as_uint(f)))

// ---------------------------------------------------------------------------
// Kernel 1: pack adjacency -> bitmask. One warp packs 256 ints (MLP=8).
// ---------------------------------------------------------------------------
__global__ void __launch_bounds__(256) pack_adj_kernel(const int* __restrict__ adj) {
    int warp = (blockIdx.x * blockDim.x + threadIdx.x) >> 5;
    int lane = threadIdx.x & 31;
    size_t base = (size_t)warp * 256;

    int v0 = adj[base +   0 + lane]; int v1 = adj[base +  32 + lane];
    int v2 = adj[base +  64 + lane]; int v3 = adj[base +  96 + lane];
    int v4 = adj[base + 128 + lane]; int v5 = adj[base + 160 + lane];
    int v6 = adj[base + 192 + lane]; int v7 = adj[base + 224 + lane];

    unsigned m0 = __ballot_sync(0xffffffffu, v0 != 0);
    unsigned m1 = __ballot_sync(0xffffffffu, v1 != 0);
    unsigned m2 = __ballot_sync(0xffffffffu, v2 != 0);
    unsigned m3 = __ballot_sync(0xffffffffu, v3 != 0);
    unsigned m4 = __ballot_sync(0xffffffffu, v4 != 0);
    unsigned m5 = __ballot_sync(0xffffffffu, v5 != 0);
    unsigned m6 = __ballot_sync(0xffffffffu, v6 != 0);
    unsigned m7 = __ballot_sync(0xffffffffu, v7 != 0);

    if (lane == 0) {
        uint4* o = (uint4*)&g_adj[(size_t)warp * 8];
        o[0] = make_uint4(m0, m1, m2, m3);
        o[1] = make_uint4(m4, m5, m6, m7);
    }
}

// ---------------------------------------------------------------------------
// Kernel 2: h_prime GEMM + tanh + src/dst dots + exp tables. FFMA2 inner loop.
// ---------------------------------------------------------------------------
__global__ void __launch_bounds__(256) hp_kernel(
    const float* __restrict__ h, const float* __restrict__ w,
    const float* __restrict__ a_src, const float* __restrict__ a_dst)
{
    int b = blockIdx.z, hd = blockIdx.y, nt = blockIdx.x;
    __shared__ float w_sh[FIN][FOUT];      // 32 KB
    __shared__ float as_sh[FOUT], ad_sh[FOUT];

    int t = threadIdx.x;
    for (int idx = t; idx < FIN * FOUT; idx += 256)
        w_sh[idx >> 6][idx & 63] = w[hd * FIN * FOUT + idx];
    if (t < FOUT) { as_sh[t] = a_src[hd * FOUT + t]; ad_sh[t] = a_dst[hd * FOUT + t]; }
    __syncthreads();

    int nl = t >> 3, og = t & 7;
    int n = nt * 32 + nl;
    const float* hrow = h + ((size_t)b * NN + n) * FIN;

    u64 acc[4] = {0ull, 0ull, 0ull, 0ull};
    #pragma unroll 8
    for (int f = 0; f < FIN; f++) {
        float hv = __ldg(hrow + f);
        u64 pp; PACK2(pp, hv);
        const ulonglong2* wp = (const ulonglong2*)&w_sh[f][og * 8];
        ulonglong2 w0 = wp[0], w1 = wp[1];
        FMA2(acc[0], pp, w0.x); FMA2(acc[1], pp, w0.y);
        FMA2(acc[2], pp, w1.x); FMA2(acc[3], pp, w1.y);
    }

    float av[8];
    #pragma unroll
    for (int q = 0; q < 4; q++) {
        uint2 u = *(uint2*)&acc[q];
        av[2*q]   = __uint_as_float(u.x);
        av[2*q+1] = __uint_as_float(u.y);
    }

    size_t base = ((size_t)(b * NH + hd) * NN + n) * FOUT + og * 8;
    float4* o4 = (float4*)&g_hp[base];
    o4[0] = make_float4(av[0], av[1], av[2], av[3]);
    o4[1] = make_float4(av[4], av[5], av[6], av[7]);

    float ps = 0.f, pd = 0.f;
    #pragma unroll
    for (int k = 0; k < 8; k++) {
        float tv = tanhf(av[k]);
        ps += tv * as_sh[og * 8 + k];
        pd += tv * ad_sh[og * 8 + k];
    }
    #pragma unroll
    for (int off = 4; off; off >>= 1) {
        ps += __shfl_down_sync(0xffffffffu, ps, off, 8);
        pd += __shfl_down_sync(0xffffffffu, pd, off, 8);
    }
    if (og == 0) {
        int idx = (b * NH + hd) * NN + n;
        g_src[idx]  = ps; g_Es[idx] = expf(ps); g_E2s[idx] = expf(NEG * ps);
        g_dstv[idx] = pd; g_Fd[idx] = expf(pd); g_F2d[idx] = expf(NEG * pd);
    }
}

// ---------------------------------------------------------------------------
// Kernel 3: attention GEMM. 256 threads; thread tile = 2 rows x 16 cols.
// ig = t>>2 (64 groups x 2 rows = 128 i-rows), og = t&3 (4 groups x 16 cols).
// FFMA2 accumulators (8 packed pairs per row).
// ---------------------------------------------------------------------------
__global__ void __launch_bounds__(256) attn_kernel(
    const float* __restrict__ bias, float* __restrict__ out)
{
    int b = blockIdx.z, hd = blockIdx.y, it = blockIdx.x;
    int i0 = it * 128;
    __shared__ ulonglong2 hp_sh[32][16];   // 8 KB: [j][64 cols as 16B chunks]
    __shared__ float4     dFF[32];         // (dst, Fd, F2d, -) per j
    __shared__ unsigned   adj_sh[128];

    int t = threadIdx.x;
    int ig = t >> 2, og = t & 3;
    int og4 = og * 4;
    int bh = (b * NH + hd) * NN;

    float srcv[2], Es[2], E2s[2], S[2] = {0.f, 0.f};
    u64 acc[2][8];
    #pragma unroll
    for (int r = 0; r < 2; r++) {
        int gi = bh + i0 + ig * 2 + r;
        srcv[r] = g_src[gi]; Es[r] = g_Es[gi]; E2s[r] = g_E2s[gi];
        #pragma unroll
        for (int q = 0; q < 8; q++) acc[r][q] = 0ull;
    }

    const float* hp = g_hp + (size_t)bh * FOUT;

    for (int jt = 0; jt < 32; jt++) {
        int j0 = jt * 32;
        #pragma unroll
        for (int idx = t; idx < 512; idx += 256) {
            int j = idx >> 4, c = idx & 15;
            hp_sh[j][c] = ((const ulonglong2*)(hp + (size_t)(j0 + j) * FOUT))[c];
        }
        if (t < 32) {
            int gi = bh + j0 + t;
            dFF[t] = make_float4(g_dstv[gi], g_Fd[gi], g_F2d[gi], 0.f);
        }
        if (t >= 128) {
            int ii = t - 128;
            adj_sh[ii] = g_adj[((size_t)b * NN + i0 + ii) * NW + jt];
        }
        __syncthreads();

        unsigned aw0 = adj_sh[ig * 2];
        unsigned aw1 = adj_sh[ig * 2 + 1];

        #pragma unroll 4
        for (int j = 0; j < 32; j++) {
            float4 dv = dFF[j];
            ulonglong2 h0 = hp_sh[j][og4];
            ulonglong2 h1 = hp_sh[j][og4 + 1];
            ulonglong2 h2 = hp_sh[j][og4 + 2];
            ulonglong2 h3 = hp_sh[j][og4 + 3];

            // row 0
            {
                float x = srcv[0] + dv.x;
                float p = (x >= 0.f) ? Es[0] * dv.y : E2s[0] * dv.z;
                p = ((aw0 >> j) & 1u) ? p : 0.f;
                S[0] += p;
                u64 pp; PACK2(pp, p);
                FMA2(acc[0][0], pp, h0.x); FMA2(acc[0][1], pp, h0.y);
                FMA2(acc[0][2], pp, h1.x); FMA2(acc[0][3], pp, h1.y);
                FMA2(acc[0][4], pp, h2.x); FMA2(acc[0][5], pp, h2.y);
                FMA2(acc[0][6], pp, h3.x); FMA2(acc[0][7], pp, h3.y);
            }
            // row 1
            {
                float x = srcv[1] + dv.x;
                float p = (x >= 0.f) ? Es[1] * dv.y : E2s[1] * dv.z;
                p = ((aw1 >> j) & 1u) ? p : 0.f;
                S[1] += p;
                u64 pp; PACK2(pp, p);
                FMA2(acc[1][0], pp, h0.x); FMA2(acc[1][1], pp, h0.y);
                FMA2(acc[1][2], pp, h1.x); FMA2(acc[1][3], pp, h1.y);
                FMA2(acc[1][4], pp, h2.x); FMA2(acc[1][5], pp, h2.y);
                FMA2(acc[1][6], pp, h3.x); FMA2(acc[1][7], pp, h3.y);
            }
        }
        __syncthreads();
    }

    float bv[16];
    #pragma unroll
    for (int k = 0; k < 16; k++) bv[k] = bias[og * 16 + k];

    #pragma unroll
    for (int r = 0; r < 2; r++) {
        float inv = 1.0f / S[r];
        float v[16];
        #pragma unroll
        for (int q = 0; q < 8; q++) {
            uint2 u = *(uint2*)&acc[r][q];
            v[2*q]   = __uint_as_float(u.x) * inv + bv[2*q];
            v[2*q+1] = __uint_as_float(u.y) * inv + bv[2*q+1];
        }
        size_t base = ((size_t)bh + i0 + ig * 2 + r) * FOUT + og * 16;
        float4* o4 = (float4*)&out[base];
        o4[0] = make_float4(v[0],  v[1],  v[2],  v[3]);
        o4[1] = make_float4(v[4],  v[5],  v[6],  v[7]);
        o4[2] = make_float4(v[8],  v[9],  v[10], v[11]);
        o4[3] = make_float4(v[12], v[13], v[14], v[15]);
    }
}

// ---------------------------------------------------------------------------
extern "C" void kernel_launch(void* const* d_in, const int* in_sizes, int n_in,
                              void* d_out, int out_size)
{
    const float* h     = (const float*)d_in[0];
    const int*   adj   = (const int*)  d_in[1];
    const float* w     = (const float*)d_in[2];
    const float* a_src = (const float*)d_in[3];
    const float* a_dst = (const float*)d_in[4];
    const float* bias  = (const float*)d_in[5];
    float* out = (float*)d_out;

    // 16M ints, 256 per warp, 8 warps per block -> 8192 blocks
    pack_adj_kernel<<<(BS * NN * NN) / 2048, 256>>>(adj);
    hp_kernel<<<dim3(NN / 32, NH, BS), 256>>>(h, w, a_src, a_dst);
    attn_kernel<<<dim3(NN / 128, NH, BS), 256>>>(bias, out);
}

// round 5
// speedup vs baseline: 2.6257x; 2.6257x over previous
#include <cuda_runtime.h>
#include <cuda_bf16.h>
#include <cstdint>

#define BS   16
#define NN   1024
#define FIN  128
#define FOUT 64
#define NH   4
#define NEG  0.2f
#define NW   32          // adj words per row

typedef unsigned int       u32;
typedef unsigned long long u64;

// ---- scratch ----
__device__ __nv_bfloat16 g_hpT_hi[(size_t)BS*NH*FOUT*NN];  // 8 MB [bh][o][j] K-major
__device__ __nv_bfloat16 g_hpT_lo[(size_t)BS*NH*FOUT*NN];  // 8 MB
__device__ unsigned      g_adj[(size_t)BS*NN*NW];          // 2 MB bitmask
__device__ float4        g_sE [BS*NH*NN];                  // (src, e^src, e^.2src, -)
__device__ float4        g_dFF[BS*NH*NN];                  // (dst, e^dst, e^.2dst, -)

// ---------------------------------------------------------------------------
// Kernel 1: pack adjacency -> bitmask. One warp packs 256 ints (MLP=8).
// ---------------------------------------------------------------------------
__global__ void __launch_bounds__(256) pack_adj_kernel(const int* __restrict__ adj) {
    int warp = (blockIdx.x * blockDim.x + threadIdx.x) >> 5;
    int lane = threadIdx.x & 31;
    size_t base = (size_t)warp * 256;
    int v0 = adj[base +   0 + lane]; int v1 = adj[base +  32 + lane];
    int v2 = adj[base +  64 + lane]; int v3 = adj[base +  96 + lane];
    int v4 = adj[base + 128 + lane]; int v5 = adj[base + 160 + lane];
    int v6 = adj[base + 192 + lane]; int v7 = adj[base + 224 + lane];
    unsigned m0 = __ballot_sync(~0u, v0 != 0), m1 = __ballot_sync(~0u, v1 != 0);
    unsigned m2 = __ballot_sync(~0u, v2 != 0), m3 = __ballot_sync(~0u, v3 != 0);
    unsigned m4 = __ballot_sync(~0u, v4 != 0), m5 = __ballot_sync(~0u, v5 != 0);
    unsigned m6 = __ballot_sync(~0u, v6 != 0), m7 = __ballot_sync(~0u, v7 != 0);
    if (lane == 0) {
        uint4* o = (uint4*)&g_adj[(size_t)warp * 8];
        o[0] = make_uint4(m0, m1, m2, m3);
        o[1] = make_uint4(m4, m5, m6, m7);
    }
}

// ---------------------------------------------------------------------------
// Kernel 2: h_prime GEMM + tanh + src/dst tables; writes TRANSPOSED bf16
// hi/lo split hp to g_hpT_{hi,lo}[o][j] (K-major B operand for attention MMA).
// ---------------------------------------------------------------------------
__global__ void __launch_bounds__(256) hp_kernel(
    const float* __restrict__ h, const float* __restrict__ w,
    const float* __restrict__ a_src, const float* __restrict__ a_dst)
{
    int b = blockIdx.z, hd = blockIdx.y, nt = blockIdx.x;
    __shared__ float w_sh[FIN][FOUT];      // 32 KB
    __shared__ float stage[32][65];        // transpose staging
    __shared__ float as_sh[FOUT], ad_sh[FOUT];

    int t = threadIdx.x;
    for (int idx = t; idx < FIN * FOUT; idx += 256)
        w_sh[idx >> 6][idx & 63] = w[hd * FIN * FOUT + idx];
    if (t < FOUT) { as_sh[t] = a_src[hd * FOUT + t]; ad_sh[t] = a_dst[hd * FOUT + t]; }
    __syncthreads();

    int nl = t >> 3, og = t & 7;
    int n = nt * 32 + nl;
    const float* hrow = h + ((size_t)b * NN + n) * FIN;

    float acc[8] = {0.f,0.f,0.f,0.f,0.f,0.f,0.f,0.f};
    #pragma unroll 8
    for (int f = 0; f < FIN; f++) {
        float hv = __ldg(hrow + f);
        const float4* wr = (const float4*)&w_sh[f][og * 8];
        float4 w0 = wr[0], w1 = wr[1];
        acc[0] += hv * w0.x; acc[1] += hv * w0.y;
        acc[2] += hv * w0.z; acc[3] += hv * w0.w;
        acc[4] += hv * w1.x; acc[5] += hv * w1.y;
        acc[6] += hv * w1.z; acc[7] += hv * w1.w;
    }
    #pragma unroll
    for (int k = 0; k < 8; k++) stage[nl][og * 8 + k] = acc[k];

    float ps = 0.f, pd = 0.f;
    #pragma unroll
    for (int k = 0; k < 8; k++) {
        float tv = tanhf(acc[k]);
        ps += tv * as_sh[og * 8 + k];
        pd += tv * ad_sh[og * 8 + k];
    }
    #pragma unroll
    for (int off = 4; off; off >>= 1) {
        ps += __shfl_down_sync(~0u, ps, off, 8);
        pd += __shfl_down_sync(~0u, pd, off, 8);
    }
    if (og == 0) {
        int idx = (b * NH + hd) * NN + n;
        g_sE [idx] = make_float4(ps, expf(ps), expf(NEG * ps), 0.f);
        g_dFF[idx] = make_float4(pd, expf(pd), expf(NEG * pd), 0.f);
    }
    __syncthreads();

    // transpose + bf16 hi/lo split: thread -> (o = t>>2, 8-n chunk c = t&3)
    {
        int o = t >> 2, c = t & 3;
        int bh64 = (b * NH + hd) * FOUT;
        u32 uh[4], ul[4];
        #pragma unroll
        for (int q = 0; q < 4; q++) {
            float p0 = stage[c * 8 + q * 2][o];
            float p1 = stage[c * 8 + q * 2 + 1][o];
            u32 b0 = __float_as_uint(p0), b1 = __float_as_uint(p1);
            uh[q] = __byte_perm(b0, b1, 0x7632);
            float l0 = p0 - __uint_as_float(b0 & 0xFFFF0000u);
            float l1 = p1 - __uint_as_float(b1 & 0xFFFF0000u);
            asm("cvt.rn.bf16x2.f32 %0, %1, %2;" : "=r"(ul[q]) : "f"(l1), "f"(l0));
        }
        size_t off = (size_t)(bh64 + o) * NN + nt * 32 + c * 8;
        *(uint4*)&g_hpT_hi[off] = make_uint4(uh[0], uh[1], uh[2], uh[3]);
        *(uint4*)&g_hpT_lo[off] = make_uint4(ul[0], ul[1], ul[2], ul[3]);
    }
}

// ---------------------------------------------------------------------------
// Kernel 3: attention via mma.sync m16n8k16 bf16 with exact hi/lo split.
// Block = (128 i, head, batch), 256 threads = 8 warps; warp w owns i-rows
// [16w,16w+16). Per 32-j chunk: stage hp hi/lo in smem [64 o][40 k-padded];
// P generated straight into A-fragments; 24 HMMA per warp per 16-k step.
// ---------------------------------------------------------------------------
#define BSTRIDE 40   // bf16 elems per smem B row (bank-conflict-free ldmatrix)

#define MMA_BF16(C, A, b0, b1)                                                 \
    asm volatile("mma.sync.aligned.m16n8k16.row.col.f32.bf16.bf16.f32 "        \
        "{%0,%1,%2,%3}, {%4,%5,%6,%7}, {%8,%9}, {%0,%1,%2,%3};"                \
        : "+f"((C)[0]), "+f"((C)[1]), "+f"((C)[2]), "+f"((C)[3])               \
        : "r"((A)[0]), "r"((A)[1]), "r"((A)[2]), "r"((A)[3]), "r"(b0), "r"(b1))

#define LDMX4(r0, r1, r2, r3, a)                                               \
    asm volatile("ldmatrix.sync.aligned.m8n8.x4.shared.b16 {%0,%1,%2,%3}, [%4];" \
        : "=r"(r0), "=r"(r1), "=r"(r2), "=r"(r3) : "r"(a))

__global__ void __launch_bounds__(256) attn_mma_kernel(
    const float* __restrict__ bias, float* __restrict__ out)
{
    __shared__ __align__(16) __nv_bfloat16 Bhi[64 * BSTRIDE];
    __shared__ __align__(16) __nv_bfloat16 Blo[64 * BSTRIDE];
    __shared__ float4 dffs[32];

    int t = threadIdx.x;
    int lane = t & 31, w = t >> 5;
    int q = lane & 3, g = lane >> 2;
    int b = blockIdx.z, hd = blockIdx.y, it = blockIdx.x;
    int i0 = it * 128;
    int bh = (b * NH + hd) * NN;
    int bh64 = (b * NH + hd) * FOUT;

    int ia = i0 + w * 16 + g;
    int ib = ia + 8;
    float4 sea = g_sE[bh + ia];
    float4 seb = g_sE[bh + ib];
    const unsigned* awa_p = g_adj + (size_t)(b * NN + ia) * NW;
    const unsigned* awb_p = g_adj + (size_t)(b * NN + ib) * NW;

    float Sa = 0.f, Sb = 0.f;
    float C[8][4];
    #pragma unroll
    for (int ot = 0; ot < 8; ot++) {
        C[ot][0] = 0.f; C[ot][1] = 0.f; C[ot][2] = 0.f; C[ot][3] = 0.f;
    }

    // stage-fill mapping: row = o (t>>2), seg = 16B chunk (t&3)
    int srow = t >> 2, sseg = t & 3;
    const uint4* ghi = (const uint4*)(g_hpT_hi + (size_t)(bh64 + srow) * NN);
    const uint4* glo = (const uint4*)(g_hpT_lo + (size_t)(bh64 + srow) * NN);
    __nv_bfloat16* bhid = &Bhi[srow * BSTRIDE + sseg * 8];
    __nv_bfloat16* blod = &Blo[srow * BSTRIDE + sseg * 8];

    // ldmatrix per-lane term: n-row = (l&7) + ((l>>4)&1)*8, k-add = ((l>>3)&1)*8
    u32 lmterm = (u32)(((lane & 7) + ((lane >> 4) & 1) * 8) * BSTRIDE
                       + ((lane >> 3) & 1) * 8);
    u32 BhiB = (u32)__cvta_generic_to_shared(Bhi);
    u32 BloB = (u32)__cvta_generic_to_shared(Blo);

    for (int jt = 0; jt < 32; jt++) {
        uint4 vh = ghi[jt * 4 + sseg];
        uint4 vl = glo[jt * 4 + sseg];
        float4 dtmp;
        if (t < 32) dtmp = g_dFF[bh + jt * 32 + t];
        __syncthreads();                 // previous chunk fully consumed
        *(uint4*)bhid = vh;
        *(uint4*)blod = vl;
        if (t < 32) dffs[t] = dtmp;
        __syncthreads();                 // stage visible

        unsigned awa = __ldg(awa_p + jt);
        unsigned awb = __ldg(awb_p + jt);

        #pragma unroll
        for (int ks = 0; ks < 2; ks++) {
            int jb = ks * 16;
            float4 d0 = dffs[jb + 2 * q];
            float4 d1 = dffs[jb + 2 * q + 1];
            float4 d2 = dffs[jb + 2 * q + 8];
            float4 d3 = dffs[jb + 2 * q + 9];

            float pa[4], pb[4];
            {
                float x;
                x = sea.x + d0.x; pa[0] = (x >= 0.f) ? sea.y * d0.y : sea.z * d0.z;
                x = sea.x + d1.x; pa[1] = (x >= 0.f) ? sea.y * d1.y : sea.z * d1.z;
                x = sea.x + d2.x; pa[2] = (x >= 0.f) ? sea.y * d2.y : sea.z * d2.z;
                x = sea.x + d3.x; pa[3] = (x >= 0.f) ? sea.y * d3.y : sea.z * d3.z;
                x = seb.x + d0.x; pb[0] = (x >= 0.f) ? seb.y * d0.y : seb.z * d0.z;
                x = seb.x + d1.x; pb[1] = (x >= 0.f) ? seb.y * d1.y : seb.z * d1.z;
                x = seb.x + d2.x; pb[2] = (x >= 0.f) ? seb.y * d2.y : seb.z * d2.z;
                x = seb.x + d3.x; pb[3] = (x >= 0.f) ? seb.y * d3.y : seb.z * d3.z;
            }
            pa[0] = ((awa >> (jb + 2*q    )) & 1u) ? pa[0] : 0.f;
            pa[1] = ((awa >> (jb + 2*q + 1)) & 1u) ? pa[1] : 0.f;
            pa[2] = ((awa >> (jb + 2*q + 8)) & 1u) ? pa[2] : 0.f;
            pa[3] = ((awa >> (jb + 2*q + 9)) & 1u) ? pa[3] : 0.f;
            pb[0] = ((awb >> (jb + 2*q    )) & 1u) ? pb[0] : 0.f;
            pb[1] = ((awb >> (jb + 2*q + 1)) & 1u) ? pb[1] : 0.f;
            pb[2] = ((awb >> (jb + 2*q + 8)) & 1u) ? pb[2] : 0.f;
            pb[3] = ((awb >> (jb + 2*q + 9)) & 1u) ? pb[3] : 0.f;
            Sa += pa[0] + pa[1] + pa[2] + pa[3];
            Sb += pb[0] + pb[1] + pb[2] + pb[3];

            // A fragments: a0={A[g][2q],A[g][2q+1]}, a1=row g+8, a2/a3 = +8 k
            u32 ahi[4], alo[4];
            {
                u32 ba0 = __float_as_uint(pa[0]), ba1 = __float_as_uint(pa[1]);
                u32 ba2 = __float_as_uint(pa[2]), ba3 = __float_as_uint(pa[3]);
                u32 bb0 = __float_as_uint(pb[0]), bb1 = __float_as_uint(pb[1]);
                u32 bb2 = __float_as_uint(pb[2]), bb3 = __float_as_uint(pb[3]);
                ahi[0] = __byte_perm(ba0, ba1, 0x7632);
                ahi[1] = __byte_perm(bb0, bb1, 0x7632);
                ahi[2] = __byte_perm(ba2, ba3, 0x7632);
                ahi[3] = __byte_perm(bb2, bb3, 0x7632);
                float la0 = pa[0] - __uint_as_float(ba0 & 0xFFFF0000u);
                float la1 = pa[1] - __uint_as_float(ba1 & 0xFFFF0000u);
                float la2 = pa[2] - __uint_as_float(ba2 & 0xFFFF0000u);
                float la3 = pa[3] - __uint_as_float(ba3 & 0xFFFF0000u);
                float lb0 = pb[0] - __uint_as_float(bb0 & 0xFFFF0000u);
                float lb1 = pb[1] - __uint_as_float(bb1 & 0xFFFF0000u);
                float lb2 = pb[2] - __uint_as_float(bb2 & 0xFFFF0000u);
                float lb3 = pb[3] - __uint_as_float(bb3 & 0xFFFF0000u);
                asm("cvt.rn.bf16x2.f32 %0, %1, %2;" : "=r"(alo[0]) : "f"(la1), "f"(la0));
                asm("cvt.rn.bf16x2.f32 %0, %1, %2;" : "=r"(alo[1]) : "f"(lb1), "f"(lb0));
                asm("cvt.rn.bf16x2.f32 %0, %1, %2;" : "=r"(alo[2]) : "f"(la3), "f"(la2));
                asm("cvt.rn.bf16x2.f32 %0, %1, %2;" : "=r"(alo[3]) : "f"(lb3), "f"(lb2));
            }

            #pragma unroll
            for (int pr = 0; pr < 4; pr++) {
                u32 aoff = (u32)((pr * 16 * BSTRIDE + ks * 16) * 2) + lmterm * 2;
                u32 h0, h1, h2, h3, l0, l1, l2, l3;
                LDMX4(h0, h1, h2, h3, BhiB + aoff);
                LDMX4(l0, l1, l2, l3, BloB + aoff);
                MMA_BF16(C[pr * 2],     ahi, h0, h1);
                MMA_BF16(C[pr * 2],     ahi, l0, l1);
                MMA_BF16(C[pr * 2],     alo, h0, h1);
                MMA_BF16(C[pr * 2 + 1], ahi, h2, h3);
                MMA_BF16(C[pr * 2 + 1], ahi, l2, l3);
                MMA_BF16(C[pr * 2 + 1], alo, h2, h3);
            }
        }
    }

    // reduce S across the quad (j-coverage split over q)
    Sa += __shfl_xor_sync(~0u, Sa, 1); Sa += __shfl_xor_sync(~0u, Sa, 2);
    Sb += __shfl_xor_sync(~0u, Sb, 1); Sb += __shfl_xor_sync(~0u, Sb, 2);
    float inva = 1.0f / Sa, invb = 1.0f / Sb;

    float* oa = out + ((size_t)bh + ia) * FOUT;
    float* ob = out + ((size_t)bh + ib) * FOUT;
    #pragma unroll
    for (int ot = 0; ot < 8; ot++) {
        int col = ot * 8 + 2 * q;
        float2 bv = __ldg((const float2*)(bias + col));
        *(float2*)(oa + col) = make_float2(C[ot][0] * inva + bv.x,
                                           C[ot][1] * inva + bv.y);
        *(float2*)(ob + col) = make_float2(C[ot][2] * invb + bv.x,
                                           C[ot][3] * invb + bv.y);
    }
}

// ---------------------------------------------------------------------------
extern "C" void kernel_launch(void* const* d_in, const int* in_sizes, int n_in,
                              void* d_out, int out_size)
{
    const float* h     = (const float*)d_in[0];
    const int*   adj   = (const int*)  d_in[1];
    const float* w     = (const float*)d_in[2];
    const float* a_src = (const float*)d_in[3];
    const float* a_dst = (const float*)d_in[4];
    const float* bias  = (const float*)d_in[5];
    float* out = (float*)d_out;

    pack_adj_kernel<<<(BS * NN * NN) / 2048, 256>>>(adj);
    hp_kernel<<<dim3(NN / 32, NH, BS), 256>>>(h, w, a_src, a_dst);
    attn_mma_kernel<<<dim3(NN / 128, NH, BS), 256>>>(bias, out);
}

// round 7
// speedup vs baseline: 2.7007x; 1.0286x over previous
#include <cuda_runtime.h>
#include <cuda_bf16.h>
#include <cstdint>

#define BS   16
#define NN   1024
#define FIN  128
#define FOUT 64
#define NH   4
#define NEG  0.2f
#define NW   32          // adj words per row

typedef unsigned int       u32;
typedef unsigned long long u64;

// ---- scratch ----
__device__ __nv_bfloat16 g_hpT_hi[(size_t)BS*NH*FOUT*NN];  // 8 MB [bh][o][j] K-major
__device__ __nv_bfloat16 g_hpT_lo[(size_t)BS*NH*FOUT*NN];  // 8 MB
__device__ unsigned      g_adj[(size_t)BS*NN*NW];          // 2 MB bitmask
__device__ float4        g_sE [BS*NH*NN];                  // (src, e^src, e^.2src, -)
__device__ float4        g_dFF[BS*NH*NN];                  // (dst, e^dst, e^.2dst, -)

// ---------------------------------------------------------------------------
// Kernel 1: pack adjacency -> bitmask. One warp packs 256 ints (MLP=8).
// ---------------------------------------------------------------------------
__global__ void __launch_bounds__(256) pack_adj_kernel(const int* __restrict__ adj) {
    int warp = (blockIdx.x * blockDim.x + threadIdx.x) >> 5;
    int lane = threadIdx.x & 31;
    size_t base = (size_t)warp * 256;
    int v0 = adj[base +   0 + lane]; int v1 = adj[base +  32 + lane];
    int v2 = adj[base +  64 + lane]; int v3 = adj[base +  96 + lane];
    int v4 = adj[base + 128 + lane]; int v5 = adj[base + 160 + lane];
    int v6 = adj[base + 192 + lane]; int v7 = adj[base + 224 + lane];
    unsigned m0 = __ballot_sync(~0u, v0 != 0), m1 = __ballot_sync(~0u, v1 != 0);
    unsigned m2 = __ballot_sync(~0u, v2 != 0), m3 = __ballot_sync(~0u, v3 != 0);
    unsigned m4 = __ballot_sync(~0u, v4 != 0), m5 = __ballot_sync(~0u, v5 != 0);
    unsigned m6 = __ballot_sync(~0u, v6 != 0), m7 = __ballot_sync(~0u, v7 != 0);
    if (lane == 0) {
        uint4* o = (uint4*)&g_adj[(size_t)warp * 8];
        o[0] = make_uint4(m0, m1, m2, m3);
        o[1] = make_uint4(m4, m5, m6, m7);
    }
}

// ---------------------------------------------------------------------------
// Kernel 2: h_prime GEMM + tanh + src/dst tables; writes TRANSPOSED bf16
// hi/lo split hp to g_hpT_{hi,lo}[o][j] (K-major B operand for attention MMA).
// ---------------------------------------------------------------------------
__global__ void __launch_bounds__(256) hp_kernel(
    const float* __restrict__ h, const float* __restrict__ w,
    const float* __restrict__ a_src, const float* __restrict__ a_dst)
{
    int b = blockIdx.z, hd = blockIdx.y, nt = blockIdx.x;
    __shared__ float w_sh[FIN][FOUT];      // 32 KB
    __shared__ float stage[32][65];        // transpose staging
    __shared__ float as_sh[FOUT], ad_sh[FOUT];

    int t = threadIdx.x;
    for (int idx = t; idx < FIN * FOUT; idx += 256)
        w_sh[idx >> 6][idx & 63] = w[hd * FIN * FOUT + idx];
    if (t < FOUT) { as_sh[t] = a_src[hd * FOUT + t]; ad_sh[t] = a_dst[hd * FOUT + t]; }
    __syncthreads();

    int nl = t >> 3, og = t & 7;
    int n = nt * 32 + nl;
    const float* hrow = h + ((size_t)b * NN + n) * FIN;

    float acc[8] = {0.f,0.f,0.f,0.f,0.f,0.f,0.f,0.f};
    #pragma unroll 8
    for (int f = 0; f < FIN; f++) {
        float hv = __ldg(hrow + f);
        const float4* wr = (const float4*)&w_sh[f][og * 8];
        float4 w0 = wr[0], w1 = wr[1];
        acc[0] += hv * w0.x; acc[1] += hv * w0.y;
        acc[2] += hv * w0.z; acc[3] += hv * w0.w;
        acc[4] += hv * w1.x; acc[5] += hv * w1.y;
        acc[6] += hv * w1.z; acc[7] += hv * w1.w;
    }
    #pragma unroll
    for (int k = 0; k < 8; k++) stage[nl][og * 8 + k] = acc[k];

    float ps = 0.f, pd = 0.f;
    #pragma unroll
    for (int k = 0; k < 8; k++) {
        float tv = tanhf(acc[k]);
        ps += tv * as_sh[og * 8 + k];
        pd += tv * ad_sh[og * 8 + k];
    }
    #pragma unroll
    for (int off = 4; off; off >>= 1) {
        ps += __shfl_down_sync(~0u, ps, off, 8);
        pd += __shfl_down_sync(~0u, pd, off, 8);
    }
    if (og == 0) {
        int idx = (b * NH + hd) * NN + n;
        g_sE [idx] = make_float4(ps, expf(ps), expf(NEG * ps), 0.f);
        g_dFF[idx] = make_float4(pd, expf(pd), expf(NEG * pd), 0.f);
    }
    __syncthreads();

    // transpose + bf16 hi/lo split: thread -> (o = t>>2, 8-n chunk c = t&3)
    {
        int o = t >> 2, c = t & 3;
        int bh64 = (b * NH + hd) * FOUT;
        u32 uh[4], ul[4];
        #pragma unroll
        for (int q = 0; q < 4; q++) {
            float p0 = stage[c * 8 + q * 2][o];
            float p1 = stage[c * 8 + q * 2 + 1][o];
            u32 b0 = __float_as_uint(p0), b1 = __float_as_uint(p1);
            uh[q] = __byte_perm(b0, b1, 0x7632);
            float l0 = p0 - __uint_as_float(b0 & 0xFFFF0000u);
            float l1 = p1 - __uint_as_float(b1 & 0xFFFF0000u);
            asm("cvt.rn.bf16x2.f32 %0, %1, %2;" : "=r"(ul[q]) : "f"(l1), "f"(l0));
        }
        size_t off = (size_t)(bh64 + o) * NN + nt * 32 + c * 8;
        *(uint4*)&g_hpT_hi[off] = make_uint4(uh[0], uh[1], uh[2], uh[3]);
        *(uint4*)&g_hpT_lo[off] = make_uint4(ul[0], ul[1], ul[2], ul[3]);
    }
}

// ---------------------------------------------------------------------------
// Kernel 3: attention via mma.sync m16n8k16 bf16 with exact hi/lo split.
// 3-stage cp.async pipeline. Loop order: wait -> barrier -> issue -> consume,
// so the stage being overwritten was fully consumed by ALL threads (the
// barrier), fixing the round-6 WAR race while keeping one barrier per jt.
// ---------------------------------------------------------------------------
#define BSTRIDE 40                       // bf16 per smem B row (ldmatrix conflict-free)
#define STAGEB  (64 * BSTRIDE * 2)       // bytes per B stage (5120)

#define MMA_BF16(C, A, b0, b1)                                                 \
    asm volatile("mma.sync.aligned.m16n8k16.row.col.f32.bf16.bf16.f32 "        \
        "{%0,%1,%2,%3}, {%4,%5,%6,%7}, {%8,%9}, {%0,%1,%2,%3};"                \
        : "+f"((C)[0]), "+f"((C)[1]), "+f"((C)[2]), "+f"((C)[3])               \
        : "r"((A)[0]), "r"((A)[1]), "r"((A)[2]), "r"((A)[3]), "r"(b0), "r"(b1))

#define LDMX4(r0, r1, r2, r3, a)                                               \
    asm volatile("ldmatrix.sync.aligned.m8n8.x4.shared.b16 {%0,%1,%2,%3}, [%4];" \
        : "=r"(r0), "=r"(r1), "=r"(r2), "=r"(r3) : "r"(a))

#define CP16(dst, src) \
    asm volatile("cp.async.cg.shared.global [%0], [%1], 16;" :: "r"(dst), "l"(src) : "memory")
#define CP_COMMIT() asm volatile("cp.async.commit_group;" ::: "memory")
#define CP_WAIT1()  asm volatile("cp.async.wait_group 1;" ::: "memory")

__global__ void __launch_bounds__(256) attn_mma_kernel(
    const float* __restrict__ bias, float* __restrict__ out)
{
    __shared__ __align__(16) __nv_bfloat16 Bhi[3][64 * BSTRIDE];
    __shared__ __align__(16) __nv_bfloat16 Blo[3][64 * BSTRIDE];
    __shared__ __align__(16) float4 dffs[3][32];

    int t = threadIdx.x;
    int lane = t & 31, w = t >> 5;
    int q = lane & 3, g = lane >> 2;
    int b = blockIdx.z, hd = blockIdx.y, it = blockIdx.x;
    int i0 = it * 128;
    int bh = (b * NH + hd) * NN;
    int bh64 = (b * NH + hd) * FOUT;

    int ia = i0 + w * 16 + g;
    int ib = ia + 8;
    float4 sea = g_sE[bh + ia];
    float4 seb = g_sE[bh + ib];
    const unsigned* awa_p = g_adj + (size_t)(b * NN + ia) * NW;
    const unsigned* awb_p = g_adj + (size_t)(b * NN + ib) * NW;

    float Sa = 0.f, Sb = 0.f;
    float C[8][4];
    #pragma unroll
    for (int ot = 0; ot < 8; ot++) {
        C[ot][0] = 0.f; C[ot][1] = 0.f; C[ot][2] = 0.f; C[ot][3] = 0.f;
    }

    // staging: row = o (t>>2), seg = 16B chunk (t&3)
    int srow = t >> 2, sseg = t & 3;
    const uint4* ghi = (const uint4*)(g_hpT_hi + (size_t)(bh64 + srow) * NN);
    const uint4* glo = (const uint4*)(g_hpT_lo + (size_t)(bh64 + srow) * NN);
    u32 sBhi = (u32)__cvta_generic_to_shared(Bhi);
    u32 sBlo = (u32)__cvta_generic_to_shared(Blo);
    u32 sDff = (u32)__cvta_generic_to_shared(dffs);
    u32 doff = (u32)(srow * BSTRIDE + sseg * 8) * 2;
    const float4* dsrc = (const float4*)(g_dFF + bh) + t;   // valid when t<32

    // ldmatrix per-lane term: n-row = (l&7)+((l>>4)&1)*8, k-add = ((l>>3)&1)*8
    u32 lmterm = (u32)((((lane & 7) + ((lane >> 4) & 1) * 8) * BSTRIDE
                        + ((lane >> 3) & 1) * 8) * 2);

    #define ISSUE_STAGE(s, jtv) do {                                           \
        CP16(sBhi + (u32)(s) * STAGEB + doff, ghi + (jtv) * 4 + sseg);         \
        CP16(sBlo + (u32)(s) * STAGEB + doff, glo + (jtv) * 4 + sseg);         \
        if (t < 32) CP16(sDff + (u32)(s) * 512 + (u32)t * 16, dsrc + (jtv) * 32); \
    } while (0)

    ISSUE_STAGE(0, 0); CP_COMMIT();
    ISSUE_STAGE(1, 1); CP_COMMIT();

    unsigned awa = __ldg(awa_p), awb = __ldg(awb_p);

    for (int jt = 0; jt < 32; jt++) {
        int s = jt % 3;
        // pending groups here: {g_jt, g_jt+1}; wait_group 1 => stage s complete
        CP_WAIT1();
        __syncthreads();   // ALL threads done with stage (jt-1)%3 => safe to overwrite
        if (jt < 30) { int sn = (jt + 2) % 3; ISSUE_STAGE(sn, jt + 2); }
        CP_COMMIT();

        unsigned awa_c = awa, awb_c = awb;
        int nj = (jt < 31) ? jt + 1 : 31;
        awa = __ldg(awa_p + nj);
        awb = __ldg(awb_p + nj);

        u32 bhib = sBhi + (u32)s * STAGEB + lmterm;
        u32 blob = sBlo + (u32)s * STAGEB + lmterm;

        #pragma unroll
        for (int ks = 0; ks < 2; ks++) {
            int jb = ks * 16;
            float4 d0 = dffs[s][jb + 2 * q];
            float4 d1 = dffs[s][jb + 2 * q + 1];
            float4 d2 = dffs[s][jb + 2 * q + 8];
            float4 d3 = dffs[s][jb + 2 * q + 9];

            float pa[4], pb[4];
            {
                float x;
                x = sea.x + d0.x; pa[0] = (x >= 0.f) ? sea.y * d0.y : sea.z * d0.z;
                x = sea.x + d1.x; pa[1] = (x >= 0.f) ? sea.y * d1.y : sea.z * d1.z;
                x = sea.x + d2.x; pa[2] = (x >= 0.f) ? sea.y * d2.y : sea.z * d2.z;
                x = sea.x + d3.x; pa[3] = (x >= 0.f) ? sea.y * d3.y : sea.z * d3.z;
                x = seb.x + d0.x; pb[0] = (x >= 0.f) ? seb.y * d0.y : seb.z * d0.z;
                x = seb.x + d1.x; pb[1] = (x >= 0.f) ? seb.y * d1.y : seb.z * d1.z;
                x = seb.x + d2.x; pb[2] = (x >= 0.f) ? seb.y * d2.y : seb.z * d2.z;
                x = seb.x + d3.x; pb[3] = (x >= 0.f) ? seb.y * d3.y : seb.z * d3.z;
            }
            pa[0] = ((awa_c >> (jb + 2*q    )) & 1u) ? pa[0] : 0.f;
            pa[1] = ((awa_c >> (jb + 2*q + 1)) & 1u) ? pa[1] : 0.f;
            pa[2] = ((awa_c >> (jb + 2*q + 8)) & 1u) ? pa[2] : 0.f;
            pa[3] = ((awa_c >> (jb + 2*q + 9)) & 1u) ? pa[3] : 0.f;
            pb[0] = ((awb_c >> (jb + 2*q    )) & 1u) ? pb[0] : 0.f;
            pb[1] = ((awb_c >> (jb + 2*q + 1)) & 1u) ? pb[1] : 0.f;
            pb[2] = ((awb_c >> (jb + 2*q + 8)) & 1u) ? pb[2] : 0.f;
            pb[3] = ((awb_c >> (jb + 2*q + 9)) & 1u) ? pb[3] : 0.f;
            Sa += pa[0] + pa[1] + pa[2] + pa[3];
            Sb += pb[0] + pb[1] + pb[2] + pb[3];

            u32 ahi[4], alo[4];
            {
                u32 ba0 = __float_as_uint(pa[0]), ba1 = __float_as_uint(pa[1]);
                u32 ba2 = __float_as_uint(pa[2]), ba3 = __float_as_uint(pa[3]);
                u32 bb0 = __float_as_uint(pb[0]), bb1 = __float_as_uint(pb[1]);
                u32 bb2 = __float_as_uint(pb[2]), bb3 = __float_as_uint(pb[3]);
                ahi[0] = __byte_perm(ba0, ba1, 0x7632);
                ahi[1] = __byte_perm(bb0, bb1, 0x7632);
                ahi[2] = __byte_perm(ba2, ba3, 0x7632);
                ahi[3] = __byte_perm(bb2, bb3, 0x7632);
                float la0 = pa[0] - __uint_as_float(ba0 & 0xFFFF0000u);
                float la1 = pa[1] - __uint_as_float(ba1 & 0xFFFF0000u);
                float la2 = pa[2] - __uint_as_float(ba2 & 0xFFFF0000u);
                float la3 = pa[3] - __uint_as_float(ba3 & 0xFFFF0000u);
                float lb0 = pb[0] - __uint_as_float(bb0 & 0xFFFF0000u);
                float lb1 = pb[1] - __uint_as_float(bb1 & 0xFFFF0000u);
                float lb2 = pb[2] - __uint_as_float(bb2 & 0xFFFF0000u);
                float lb3 = pb[3] - __uint_as_float(bb3 & 0xFFFF0000u);
                asm("cvt.rn.bf16x2.f32 %0, %1, %2;" : "=r"(alo[0]) : "f"(la1), "f"(la0));
                asm("cvt.rn.bf16x2.f32 %0, %1, %2;" : "=r"(alo[1]) : "f"(lb1), "f"(lb0));
                asm("cvt.rn.bf16x2.f32 %0, %1, %2;" : "=r"(alo[2]) : "f"(la3), "f"(la2));
                asm("cvt.rn.bf16x2.f32 %0, %1, %2;" : "=r"(alo[3]) : "f"(lb3), "f"(lb2));
            }

            #pragma unroll
            for (int pr = 0; pr < 4; pr++) {
                u32 aoff = (u32)((pr * 16 * BSTRIDE + ks * 16) * 2);
                u32 h0, h1, h2, h3, l0, l1, l2, l3;
                LDMX4(h0, h1, h2, h3, bhib + aoff);
                LDMX4(l0, l1, l2, l3, blob + aoff);
                // interleaved: same-C ops spaced by 2 -> chain stalls hidden
                MMA_BF16(C[pr * 2],     ahi, h0, h1);
                MMA_BF16(C[pr * 2 + 1], ahi, h2, h3);
                MMA_BF16(C[pr * 2],     ahi, l0, l1);
                MMA_BF16(C[pr * 2 + 1], ahi, l2, l3);
                MMA_BF16(C[pr * 2],     alo, h0, h1);
                MMA_BF16(C[pr * 2 + 1], alo, h2, h3);
            }
        }
    }

    // reduce S across the quad (j-coverage split over q)
    Sa += __shfl_xor_sync(~0u, Sa, 1); Sa += __shfl_xor_sync(~0u, Sa, 2);
    Sb += __shfl_xor_sync(~0u, Sb, 1); Sb += __shfl_xor_sync(~0u, Sb, 2);
    float inva = 1.0f / Sa, invb = 1.0f / Sb;

    float* oa = out + ((size_t)bh + ia) * FOUT;
    float* ob = out + ((size_t)bh + ib) * FOUT;
    #pragma unroll
    for (int ot = 0; ot < 8; ot++) {
        int col = ot * 8 + 2 * q;
        float2 bv = __ldg((const float2*)(bias + col));
        *(float2*)(oa + col) = make_float2(C[ot][0] * inva + bv.x,
                                           C[ot][1] * inva + bv.y);
        *(float2*)(ob + col) = make_float2(C[ot][2] * invb + bv.x,
                                           C[ot][3] * invb + bv.y);
    }
}

// ---------------------------------------------------------------------------
extern "C" void kernel_launch(void* const* d_in, const int* in_sizes, int n_in,
                              void* d_out, int out_size)
{
    const float* h     = (const float*)d_in[0];
    const int*   adj   = (const int*)  d_in[1];
    const float* w     = (const float*)d_in[2];
    const float* a_src = (const float*)d_in[3];
    const float* a_dst = (const float*)d_in[4];
    const float* bias  = (const float*)d_in[5];
    float* out = (float*)d_out;

    pack_adj_kernel<<<(BS * NN * NN) / 2048, 256>>>(adj);
    hp_kernel<<<dim3(NN / 32, NH, BS), 256>>>(h, w, a_src, a_dst);
    attn_mma_kernel<<<dim3(NN / 128, NH, BS), 256>>>(bias, out);
}

// round 9
// speedup vs baseline: 2.9313x; 1.0854x over previous
#include <cuda_runtime.h>
#include <cuda_fp16.h>
#include <cstdint>

#define BS   16
#define NN   1024
#define FIN  128
#define FOUT 64
#define NH   4
#define NEG  0.2f
#define NW   32          // adj words per row

typedef unsigned int       u32;
typedef unsigned long long u64;

// ---- scratch ----
__device__ __half    g_hpT_hi[(size_t)BS*NH*FOUT*NN];  // 8 MB [bh][o][j] K-major fp16 hi
__device__ __half    g_hpT_lo[(size_t)BS*NH*FOUT*NN];  // 8 MB fp16 lo (exact residual)
__device__ unsigned  g_adj[(size_t)BS*NN*NW];          // 2 MB bitmask
__device__ float4    g_sE [BS*NH*NN];   // (src, 2^-k*e^src, 2^-k*e^.2src, -)  k=rint(src*log2e)
__device__ float4    g_dFF[BS*NH*NN];   // (dst, e^dst, e^.2dst, -)

// ---------------------------------------------------------------------------
// Kernel 1: pack adjacency -> bitmask. One warp packs 256 ints (MLP=8).
// ---------------------------------------------------------------------------
__global__ void __launch_bounds__(256) pack_adj_kernel(const int* __restrict__ adj) {
    int warp = (blockIdx.x * blockDim.x + threadIdx.x) >> 5;
    int lane = threadIdx.x & 31;
    size_t base = (size_t)warp * 256;
    int v0 = adj[base +   0 + lane]; int v1 = adj[base +  32 + lane];
    int v2 = adj[base +  64 + lane]; int v3 = adj[base +  96 + lane];
    int v4 = adj[base + 128 + lane]; int v5 = adj[base + 160 + lane];
    int v6 = adj[base + 192 + lane]; int v7 = adj[base + 224 + lane];
    unsigned m0 = __ballot_sync(~0u, v0 != 0), m1 = __ballot_sync(~0u, v1 != 0);
    unsigned m2 = __ballot_sync(~0u, v2 != 0), m3 = __ballot_sync(~0u, v3 != 0);
    unsigned m4 = __ballot_sync(~0u, v4 != 0), m5 = __ballot_sync(~0u, v5 != 0);
    unsigned m6 = __ballot_sync(~0u, v6 != 0), m7 = __ballot_sync(~0u, v7 != 0);
    if (lane == 0) {
        uint4* o = (uint4*)&g_adj[(size_t)warp * 8];
        o[0] = make_uint4(m0, m1, m2, m3);
        o[1] = make_uint4(m4, m5, m6, m7);
    }
}

// ---------------------------------------------------------------------------
// Kernel 2: h_prime GEMM + tanh + src/dst tables; writes TRANSPOSED fp16
// hi/lo split hp. src table entries carry an exact 2^-k row rescale so the
// fp16 P operand in the attention MMA never leaves fp16 range (cancels in
// the final numerator/S ratio).
// ---------------------------------------------------------------------------
__global__ void __launch_bounds__(256) hp_kernel(
    const float* __restrict__ h, const float* __restrict__ w,
    const float* __restrict__ a_src, const float* __restrict__ a_dst)
{
    int b = blockIdx.z, hd = blockIdx.y, nt = blockIdx.x;
    __shared__ float w_sh[FIN][FOUT];      // 32 KB
    __shared__ float stage[32][65];        // transpose staging
    __shared__ float as_sh[FOUT], ad_sh[FOUT];

    int t = threadIdx.x;
    for (int idx = t; idx < FIN * FOUT; idx += 256)
        w_sh[idx >> 6][idx & 63] = w[hd * FIN * FOUT + idx];
    if (t < FOUT) { as_sh[t] = a_src[hd * FOUT + t]; ad_sh[t] = a_dst[hd * FOUT + t]; }
    __syncthreads();

    int nl = t >> 3, og = t & 7;
    int n = nt * 32 + nl;
    const float* hrow = h + ((size_t)b * NN + n) * FIN;

    float acc[8] = {0.f,0.f,0.f,0.f,0.f,0.f,0.f,0.f};
    #pragma unroll 8
    for (int f = 0; f < FIN; f++) {
        float hv = __ldg(hrow + f);
        const float4* wr = (const float4*)&w_sh[f][og * 8];
        float4 w0 = wr[0], w1 = wr[1];
        acc[0] += hv * w0.x; acc[1] += hv * w0.y;
        acc[2] += hv * w0.z; acc[3] += hv * w0.w;
        acc[4] += hv * w1.x; acc[5] += hv * w1.y;
        acc[6] += hv * w1.z; acc[7] += hv * w1.w;
    }
    #pragma unroll
    for (int k = 0; k < 8; k++) stage[nl][og * 8 + k] = acc[k];

    float ps = 0.f, pd = 0.f;
    #pragma unroll
    for (int k = 0; k < 8; k++) {
        float tv = tanhf(acc[k]);
        ps += tv * as_sh[og * 8 + k];
        pd += tv * ad_sh[og * 8 + k];
    }
    #pragma unroll
    for (int off = 4; off; off >>= 1) {
        ps += __shfl_down_sync(~0u, ps, off, 8);
        pd += __shfl_down_sync(~0u, pd, off, 8);
    }
    if (og == 0) {
        int idx = (b * NH + hd) * NN + n;
        // exact 2^-k rescale: keeps fp16 P operand in range; cancels in out = num/S
        float kf = rintf(ps * 1.44269504089f);
        float sc = ldexpf(1.0f, -(int)kf);
        g_sE [idx] = make_float4(ps, expf(ps) * sc, expf(NEG * ps) * sc, 0.f);
        g_dFF[idx] = make_float4(pd, expf(pd), expf(NEG * pd), 0.f);
    }
    __syncthreads();

    // transpose + fp16 hi/lo split: thread -> (o = t>>2, 8-n chunk c = t&3)
    {
        int o = t >> 2, c = t & 3;
        int bh64 = (b * NH + hd) * FOUT;
        u32 uh[4], ul[4];
        #pragma unroll
        for (int q = 0; q < 4; q++) {
            float p0 = stage[c * 8 + q * 2][o];
            float p1 = stage[c * 8 + q * 2 + 1][o];
            __half h0 = __float2half_rn(p0), h1 = __float2half_rn(p1);
            __half2 hh = __halves2half2(h0, h1);
            uh[q] = *(u32*)&hh;
            float l0 = p0 - __half2float(h0);
            float l1 = p1 - __half2float(h1);
            __half2 ll = __floats2half2_rn(l0, l1);
            ul[q] = *(u32*)&ll;
        }
        size_t off = (size_t)(bh64 + o) * NN + nt * 32 + c * 8;
        *(uint4*)&g_hpT_hi[off] = make_uint4(uh[0], uh[1], uh[2], uh[3]);
        *(uint4*)&g_hpT_lo[off] = make_uint4(ul[0], ul[1], ul[2], ul[3]);
    }
}

// ---------------------------------------------------------------------------
// Kernel 3: attention via mma.sync m16n8k16 fp16. P single fp16 (rn, row
// rescaled); hp split hi/lo -> 2 MMAs per k-step (was 3 with bf16 splits).
// 3-stage cp.async pipeline, one barrier per jt (wait->bar->issue->consume).
// ---------------------------------------------------------------------------
#define BSTRIDE 40                       // fp16 per smem B row (ldmatrix conflict-free)
#define STAGEB  (64 * BSTRIDE * 2)       // bytes per B stage (5120)

#define MMA_F16(C, A, b0, b1)                                                  \
    asm volatile("mma.sync.aligned.m16n8k16.row.col.f32.f16.f16.f32 "          \
        "{%0,%1,%2,%3}, {%4,%5,%6,%7}, {%8,%9}, {%0,%1,%2,%3};"                \
        : "+f"((C)[0]), "+f"((C)[1]), "+f"((C)[2]), "+f"((C)[3])               \
        : "r"((A)[0]), "r"((A)[1]), "r"((A)[2]), "r"((A)[3]), "r"(b0), "r"(b1))

#define LDMX4(r0, r1, r2, r3, a)                                               \
    asm volatile("ldmatrix.sync.aligned.m8n8.x4.shared.b16 {%0,%1,%2,%3}, [%4];" \
        : "=r"(r0), "=r"(r1), "=r"(r2), "=r"(r3) : "r"(a))

#define CP16(dst, src) \
    asm volatile("cp.async.cg.shared.global [%0], [%1], 16;" :: "r"(dst), "l"(src) : "memory")
#define CP_COMMIT() asm volatile("cp.async.commit_group;" ::: "memory")
#define CP_WAIT1()  asm volatile("cp.async.wait_group 1;" ::: "memory")

// pack two fp32 -> fp16x2 (first src -> HIGH half, matching A-frag k order)
#define PK16(dst, hi, lo) \
    asm("cvt.rn.f16x2.f32 %0, %1, %2;" : "=r"(dst) : "f"(hi), "f"(lo))

__global__ void __launch_bounds__(256) attn_mma_kernel(
    const float* __restrict__ bias, float* __restrict__ out)
{
    __shared__ __align__(16) __half Bhi[3][64 * BSTRIDE];
    __shared__ __align__(16) __half Blo[3][64 * BSTRIDE];
    __shared__ __align__(16) float4 dffs[3][32];

    int t = threadIdx.x;
    int lane = t & 31, w = t >> 5;
    int q = lane & 3, g = lane >> 2;
    int b = blockIdx.z, hd = blockIdx.y, it = blockIdx.x;
    int i0 = it * 128;
    int bh = (b * NH + hd) * NN;
    int bh64 = (b * NH + hd) * FOUT;

    int ia = i0 + w * 16 + g;
    int ib = ia + 8;
    float4 sea = g_sE[bh + ia];
    float4 seb = g_sE[bh + ib];
    const unsigned* awa_p = g_adj + (size_t)(b * NN + ia) * NW;
    const unsigned* awb_p = g_adj + (size_t)(b * NN + ib) * NW;

    float Sa = 0.f, Sb = 0.f;
    float C[8][4];
    #pragma unroll
    for (int ot = 0; ot < 8; ot++) {
        C[ot][0] = 0.f; C[ot][1] = 0.f; C[ot][2] = 0.f; C[ot][3] = 0.f;
    }

    // staging: row = o (t>>2), seg = 16B chunk (t&3)
    int srow = t >> 2, sseg = t & 3;
    const uint4* ghi = (const uint4*)(g_hpT_hi + (size_t)(bh64 + srow) * NN);
    const uint4* glo = (const uint4*)(g_hpT_lo + (size_t)(bh64 + srow) * NN);
    u32 sBhi = (u32)__cvta_generic_to_shared(Bhi);
    u32 sBlo = (u32)__cvta_generic_to_shared(Blo);
    u32 sDff = (u32)__cvta_generic_to_shared(dffs);
    u32 doff = (u32)(srow * BSTRIDE + sseg * 8) * 2;
    const float4* dsrc = (const float4*)(g_dFF + bh) + t;   // valid when t<32

    // ldmatrix per-lane term: n-row = (l&7)+((l>>4)&1)*8, k-add = ((l>>3)&1)*8
    u32 lmterm = (u32)((((lane & 7) + ((lane >> 4) & 1) * 8) * BSTRIDE
                        + ((lane >> 3) & 1) * 8) * 2);

    #define ISSUE_STAGE(s, jtv) do {                                           \
        CP16(sBhi + (u32)(s) * STAGEB + doff, ghi + (jtv) * 4 + sseg);         \
        CP16(sBlo + (u32)(s) * STAGEB + doff, glo + (jtv) * 4 + sseg);         \
        if (t < 32) CP16(sDff + (u32)(s) * 512 + (u32)t * 16, dsrc + (jtv) * 32); \
    } while (0)

    ISSUE_STAGE(0, 0); CP_COMMIT();
    ISSUE_STAGE(1, 1); CP_COMMIT();

    unsigned awa = __ldg(awa_p), awb = __ldg(awb_p);

    for (int jt = 0; jt < 32; jt++) {
        int s = jt % 3;
        // pending groups here: {g_jt, g_jt+1}; wait_group 1 => stage s complete
        CP_WAIT1();
        __syncthreads();   // ALL threads done with stage (jt-1)%3 => safe to overwrite
        if (jt < 30) { int sn = (jt + 2) % 3; ISSUE_STAGE(sn, jt + 2); }
        CP_COMMIT();

        unsigned awa_c = awa, awb_c = awb;
        int nj = (jt < 31) ? jt + 1 : 31;
        awa = __ldg(awa_p + nj);
        awb = __ldg(awb_p + nj);

        u32 bhib = sBhi + (u32)s * STAGEB + lmterm;
        u32 blob = sBlo + (u32)s * STAGEB + lmterm;

        #pragma unroll
        for (int ks = 0; ks < 2; ks++) {
            int jb = ks * 16;
            float4 d0 = dffs[s][jb + 2 * q];
            float4 d1 = dffs[s][jb + 2 * q + 1];
            float4 d2 = dffs[s][jb + 2 * q + 8];
            float4 d3 = dffs[s][jb + 2 * q + 9];

            float pa[4], pb[4];
            {
                float x;
                x = sea.x + d0.x; pa[0] = (x >= 0.f) ? sea.y * d0.y : sea.z * d0.z;
                x = sea.x + d1.x; pa[1] = (x >= 0.f) ? sea.y * d1.y : sea.z * d1.z;
                x = sea.x + d2.x; pa[2] = (x >= 0.f) ? sea.y * d2.y : sea.z * d2.z;
                x = sea.x + d3.x; pa[3] = (x >= 0.f) ? sea.y * d3.y : sea.z * d3.z;
                x = seb.x + d0.x; pb[0] = (x >= 0.f) ? seb.y * d0.y : seb.z * d0.z;
                x = seb.x + d1.x; pb[1] = (x >= 0.f) ? seb.y * d1.y : seb.z * d1.z;
                x = seb.x + d2.x; pb[2] = (x >= 0.f) ? seb.y * d2.y : seb.z * d2.z;
                x = seb.x + d3.x; pb[3] = (x >= 0.f) ? seb.y * d3.y : seb.z * d3.z;
            }
            pa[0] = ((awa_c >> (jb + 2*q    )) & 1u) ? pa[0] : 0.f;
            pa[1] = ((awa_c >> (jb + 2*q + 1)) & 1u) ? pa[1] : 0.f;
            pa[2] = ((awa_c >> (jb + 2*q + 8)) & 1u) ? pa[2] : 0.f;
            pa[3] = ((awa_c >> (jb + 2*q + 9)) & 1u) ? pa[3] : 0.f;
            pb[0] = ((awb_c >> (jb + 2*q    )) & 1u) ? pb[0] : 0.f;
            pb[1] = ((awb_c >> (jb + 2*q + 1)) & 1u) ? pb[1] : 0.f;
            pb[2] = ((awb_c >> (jb + 2*q + 8)) & 1u) ? pb[2] : 0.f;
            pb[3] = ((awb_c >> (jb + 2*q + 9)) & 1u) ? pb[3] : 0.f;
            Sa += pa[0] + pa[1] + pa[2] + pa[3];
            Sb += pb[0] + pb[1] + pb[2] + pb[3];

            // A fragments: single fp16 (rn) -- no lo split needed for P
            u32 a[4];
            PK16(a[0], pa[1], pa[0]);   // row g,   k pair lo
            PK16(a[1], pb[1], pb[0]);   // row g+8, k pair lo
            PK16(a[2], pa[3], pa[2]);   // row g,   k pair hi
            PK16(a[3], pb[3], pb[2]);   // row g+8, k pair hi

            #pragma unroll
            for (int pr = 0; pr < 4; pr++) {
                u32 aoff = (u32)((pr * 16 * BSTRIDE + ks * 16) * 2);
                u32 h0, h1, h2, h3, l0, l1, l2, l3;
                LDMX4(h0, h1, h2, h3, bhib + aoff);
                LDMX4(l0, l1, l2, l3, blob + aoff);
                // interleaved: same-C ops spaced by 2 -> chain stalls hidden
                MMA_F16(C[pr * 2],     a, h0, h1);
                MMA_F16(C[pr * 2 + 1], a, h2, h3);
                MMA_F16(C[pr * 2],     a, l0, l1);
                MMA_F16(C[pr * 2 + 1], a, l2, l3);
            }
        }
    }

    // reduce S across the quad (j-coverage split over q)
    Sa += __shfl_xor_sync(~0u, Sa, 1); Sa += __shfl_xor_sync(~0u, Sa, 2);
    Sb += __shfl_xor_sync(~0u, Sb, 1); Sb += __shfl_xor_sync(~0u, Sb, 2);
    float inva = 1.0f / Sa, invb = 1.0f / Sb;

    float* oa = out + ((size_t)bh + ia) * FOUT;
    float* ob = out + ((size_t)bh + ib) * FOUT;
    #pragma unroll
    for (int ot = 0; ot < 8; ot++) {
        int col = ot * 8 + 2 * q;
        float2 bv = __ldg((const float2*)(bias + col));
        *(float2*)(oa + col) = make_float2(C[ot][0] * inva + bv.x,
                                           C[ot][1] * inva + bv.y);
        *(float2*)(ob + col) = make_float2(C[ot][2] * invb + bv.x,
                                           C[ot][3] * invb + bv.y);
    }
}

// ---------------------------------------------------------------------------
extern "C" void kernel_launch(void* const* d_in, const int* in_sizes, int n_in,
                              void* d_out, int out_size)
{
    const float* h     = (const float*)d_in[0];
    const int*   adj   = (const int*)  d_in[1];
    const float* w     = (const float*)d_in[2];
    const float* a_src = (const float*)d_in[3];
    const float* a_dst = (const float*)d_in[4];
    const float* bias  = (const float*)d_in[5];
    float* out = (float*)d_out;

    pack_adj_kernel<<<(BS * NN * NN) / 2048, 256>>>(adj);
    hp_kernel<<<dim3(NN / 32, NH, BS), 256>>>(h, w, a_src, a_dst);
    attn_mma_kernel<<<dim3(NN / 128, NH, BS), 256>>>(bias, out);
}

// round 10
// speedup vs baseline: 3.2860x; 1.1210x over previous
#include <cuda_runtime.h>
#include <cuda_fp16.h>
#include <cstdint>

#define BS   16
#define NN   1024
#define FIN  128
#define FOUT 64
#define NH   4
#define NEG  0.2f
#define NW   32          // adj words per row

typedef unsigned int       u32;
typedef unsigned long long u64;

// ---- scratch ----
__device__ __half    g_hpT[(size_t)BS*NH*FOUT*NN];     // 8 MB [bh][o][j] K-major fp16
__device__ unsigned  g_adj[(size_t)BS*NN*NW];          // 2 MB bitmask
__device__ float4    g_sE [BS*NH*NN];   // (src, 2^-k*e^src, 2^-k*e^.2src, -)  k=rint(src*log2e)
__device__ float4    g_dFF[BS*NH*NN];   // (dst, e^dst, e^.2dst, -)

// ---------------------------------------------------------------------------
// Kernel 1: pack adjacency -> bitmask. One warp packs 256 ints (MLP=8).
// ---------------------------------------------------------------------------
__global__ void __launch_bounds__(256) pack_adj_kernel(const int* __restrict__ adj) {
    int warp = (blockIdx.x * blockDim.x + threadIdx.x) >> 5;
    int lane = threadIdx.x & 31;
    size_t base = (size_t)warp * 256;
    int v0 = adj[base +   0 + lane]; int v1 = adj[base +  32 + lane];
    int v2 = adj[base +  64 + lane]; int v3 = adj[base +  96 + lane];
    int v4 = adj[base + 128 + lane]; int v5 = adj[base + 160 + lane];
    int v6 = adj[base + 192 + lane]; int v7 = adj[base + 224 + lane];
    unsigned m0 = __ballot_sync(~0u, v0 != 0), m1 = __ballot_sync(~0u, v1 != 0);
    unsigned m2 = __ballot_sync(~0u, v2 != 0), m3 = __ballot_sync(~0u, v3 != 0);
    unsigned m4 = __ballot_sync(~0u, v4 != 0), m5 = __ballot_sync(~0u, v5 != 0);
    unsigned m6 = __ballot_sync(~0u, v6 != 0), m7 = __ballot_sync(~0u, v7 != 0);
    if (lane == 0) {
        uint4* o = (uint4*)&g_adj[(size_t)warp * 8];
        o[0] = make_uint4(m0, m1, m2, m3);
        o[1] = make_uint4(m4, m5, m6, m7);
    }
}

// ---------------------------------------------------------------------------
// Kernel 2: h_prime GEMM + tanh + src/dst tables; writes TRANSPOSED fp16 hp
// (K-major B operand). src table carries an exact 2^-k row rescale so the
// fp16 P operand never leaves range (cancels in the final numerator/S ratio).
// ---------------------------------------------------------------------------
__global__ void __launch_bounds__(256) hp_kernel(
    const float* __restrict__ h, const float* __restrict__ w,
    const float* __restrict__ a_src, const float* __restrict__ a_dst)
{
    int b = blockIdx.z, hd = blockIdx.y, nt = blockIdx.x;
    __shared__ float w_sh[FIN][FOUT];      // 32 KB
    __shared__ float stage[32][65];        // transpose staging
    __shared__ float as_sh[FOUT], ad_sh[FOUT];

    int t = threadIdx.x;
    for (int idx = t; idx < FIN * FOUT; idx += 256)
        w_sh[idx >> 6][idx & 63] = w[hd * FIN * FOUT + idx];
    if (t < FOUT) { as_sh[t] = a_src[hd * FOUT + t]; ad_sh[t] = a_dst[hd * FOUT + t]; }
    __syncthreads();

    int nl = t >> 3, og = t & 7;
    int n = nt * 32 + nl;
    const float* hrow = h + ((size_t)b * NN + n) * FIN;

    float acc[8] = {0.f,0.f,0.f,0.f,0.f,0.f,0.f,0.f};
    #pragma unroll 8
    for (int f = 0; f < FIN; f++) {
        float hv = __ldg(hrow + f);
        const float4* wr = (const float4*)&w_sh[f][og * 8];
        float4 w0 = wr[0], w1 = wr[1];
        acc[0] += hv * w0.x; acc[1] += hv * w0.y;
        acc[2] += hv * w0.z; acc[3] += hv * w0.w;
        acc[4] += hv * w1.x; acc[5] += hv * w1.y;
        acc[6] += hv * w1.z; acc[7] += hv * w1.w;
    }
    #pragma unroll
    for (int k = 0; k < 8; k++) stage[nl][og * 8 + k] = acc[k];

    float ps = 0.f, pd = 0.f;
    #pragma unroll
    for (int k = 0; k < 8; k++) {
        float tv = tanhf(acc[k]);
        ps += tv * as_sh[og * 8 + k];
        pd += tv * ad_sh[og * 8 + k];
    }
    #pragma unroll
    for (int off = 4; off; off >>= 1) {
        ps += __shfl_down_sync(~0u, ps, off, 8);
        pd += __shfl_down_sync(~0u, pd, off, 8);
    }
    if (og == 0) {
        int idx = (b * NH + hd) * NN + n;
        // exact 2^-k rescale: keeps fp16 P operand in range; cancels in out = num/S
        float kf = rintf(ps * 1.44269504089f);
        float sc = ldexpf(1.0f, -(int)kf);
        g_sE [idx] = make_float4(ps, expf(ps) * sc, expf(NEG * ps) * sc, 0.f);
        g_dFF[idx] = make_float4(pd, expf(pd), expf(NEG * pd), 0.f);
    }
    __syncthreads();

    // transpose + fp16 convert: thread -> (o = t>>2, 8-n chunk c = t&3)
    {
        int o = t >> 2, c = t & 3;
        int bh64 = (b * NH + hd) * FOUT;
        u32 uh[4];
        #pragma unroll
        for (int q = 0; q < 4; q++) {
            float p0 = stage[c * 8 + q * 2][o];
            float p1 = stage[c * 8 + q * 2 + 1][o];
            __half2 hh = __floats2half2_rn(p0, p1);
            uh[q] = *(u32*)&hh;
        }
        size_t off = (size_t)(bh64 + o) * NN + nt * 32 + c * 8;
        *(uint4*)&g_hpT[off] = make_uint4(uh[0], uh[1], uh[2], uh[3]);
    }
}

// ---------------------------------------------------------------------------
// Kernel 3: attention via mma.sync m16n8k16 fp16. P single fp16 (rn, row
// rescaled); hp single fp16 -> 1 MMA per (pr, C-tile): 16 MMAs per warp/jt.
// 3-stage cp.async pipeline, one barrier per jt (wait->bar->issue->consume).
// Smem 17 KB/block + launch_bounds(256,2) => >=2 blocks/SM for stall hiding.
// ---------------------------------------------------------------------------
#define BSTRIDE 40                       // fp16 per smem B row (ldmatrix conflict-free)
#define STAGEB  (64 * BSTRIDE * 2)       // bytes per B stage (5120)

#define MMA_F16(C, A, b0, b1)                                                  \
    asm volatile("mma.sync.aligned.m16n8k16.row.col.f32.f16.f16.f32 "          \
        "{%0,%1,%2,%3}, {%4,%5,%6,%7}, {%8,%9}, {%0,%1,%2,%3};"                \
        : "+f"((C)[0]), "+f"((C)[1]), "+f"((C)[2]), "+f"((C)[3])               \
        : "r"((A)[0]), "r"((A)[1]), "r"((A)[2]), "r"((A)[3]), "r"(b0), "r"(b1))

#define LDMX4(r0, r1, r2, r3, a)                                               \
    asm volatile("ldmatrix.sync.aligned.m8n8.x4.shared.b16 {%0,%1,%2,%3}, [%4];" \
        : "=r"(r0), "=r"(r1), "=r"(r2), "=r"(r3) : "r"(a))

#define CP16(dst, src) \
    asm volatile("cp.async.cg.shared.global [%0], [%1], 16;" :: "r"(dst), "l"(src) : "memory")
#define CP_COMMIT() asm volatile("cp.async.commit_group;" ::: "memory")
#define CP_WAIT1()  asm volatile("cp.async.wait_group 1;" ::: "memory")

// pack two fp32 -> fp16x2 (first src -> HIGH half, matching A-frag k order)
#define PK16(dst, hi, lo) \
    asm("cvt.rn.f16x2.f32 %0, %1, %2;" : "=r"(dst) : "f"(hi), "f"(lo))

__global__ void __launch_bounds__(256, 2) attn_mma_kernel(
    const float* __restrict__ bias, float* __restrict__ out)
{
    __shared__ __align__(16) __half Bt[3][64 * BSTRIDE];
    __shared__ __align__(16) float4 dffs[3][32];

    int t = threadIdx.x;
    int lane = t & 31, w = t >> 5;
    int q = lane & 3, g = lane >> 2;
    int b = blockIdx.z, hd = blockIdx.y, it = blockIdx.x;
    int i0 = it * 128;
    int bh = (b * NH + hd) * NN;
    int bh64 = (b * NH + hd) * FOUT;

    int ia = i0 + w * 16 + g;
    int ib = ia + 8;
    float4 sea = g_sE[bh + ia];
    float4 seb = g_sE[bh + ib];
    const unsigned* awa_p = g_adj + (size_t)(b * NN + ia) * NW;
    const unsigned* awb_p = g_adj + (size_t)(b * NN + ib) * NW;

    float Sa = 0.f, Sb = 0.f;
    float C[8][4];
    #pragma unroll
    for (int ot = 0; ot < 8; ot++) {
        C[ot][0] = 0.f; C[ot][1] = 0.f; C[ot][2] = 0.f; C[ot][3] = 0.f;
    }

    // staging: row = o (t>>2), seg = 16B chunk (t&3)
    int srow = t >> 2, sseg = t & 3;
    const uint4* gsrc = (const uint4*)(g_hpT + (size_t)(bh64 + srow) * NN);
    u32 sBt  = (u32)__cvta_generic_to_shared(Bt);
    u32 sDff = (u32)__cvta_generic_to_shared(dffs);
    u32 doff = (u32)(srow * BSTRIDE + sseg * 8) * 2;
    const float4* dsrc = (const float4*)(g_dFF + bh) + t;   // valid when t<32

    // ldmatrix per-lane term: n-row = (l&7)+((l>>4)&1)*8, k-add = ((l>>3)&1)*8
    u32 lmterm = (u32)((((lane & 7) + ((lane >> 4) & 1) * 8) * BSTRIDE
                        + ((lane >> 3) & 1) * 8) * 2);

    #define ISSUE_STAGE(s, jtv) do {                                           \
        CP16(sBt + (u32)(s) * STAGEB + doff, gsrc + (jtv) * 4 + sseg);         \
        if (t < 32) CP16(sDff + (u32)(s) * 512 + (u32)t * 16, dsrc + (jtv) * 32); \
    } while (0)

    ISSUE_STAGE(0, 0); CP_COMMIT();
    ISSUE_STAGE(1, 1); CP_COMMIT();

    unsigned awa = __ldg(awa_p), awb = __ldg(awb_p);

    for (int jt = 0; jt < 32; jt++) {
        int s = jt % 3;
        // pending groups here: {g_jt, g_jt+1}; wait_group 1 => stage s complete
        CP_WAIT1();
        __syncthreads();   // ALL threads done with stage (jt-1)%3 => safe to overwrite
        if (jt < 30) { int sn = (jt + 2) % 3; ISSUE_STAGE(sn, jt + 2); }
        CP_COMMIT();

        unsigned awa_c = awa, awb_c = awb;
        int nj = (jt < 31) ? jt + 1 : 31;
        awa = __ldg(awa_p + nj);
        awb = __ldg(awb_p + nj);

        u32 btb = sBt + (u32)s * STAGEB + lmterm;

        #pragma unroll
        for (int ks = 0; ks < 2; ks++) {
            int jb = ks * 16;
            float4 d0 = dffs[s][jb + 2 * q];
            float4 d1 = dffs[s][jb + 2 * q + 1];
            float4 d2 = dffs[s][jb + 2 * q + 8];
            float4 d3 = dffs[s][jb + 2 * q + 9];

            float pa[4], pb[4];
            {
                float x;
                x = sea.x + d0.x; pa[0] = (x >= 0.f) ? sea.y * d0.y : sea.z * d0.z;
                x = sea.x + d1.x; pa[1] = (x >= 0.f) ? sea.y * d1.y : sea.z * d1.z;
                x = sea.x + d2.x; pa[2] = (x >= 0.f) ? sea.y * d2.y : sea.z * d2.z;
                x = sea.x + d3.x; pa[3] = (x >= 0.f) ? sea.y * d3.y : sea.z * d3.z;
                x = seb.x + d0.x; pb[0] = (x >= 0.f) ? seb.y * d0.y : seb.z * d0.z;
                x = seb.x + d1.x; pb[1] = (x >= 0.f) ? seb.y * d1.y : seb.z * d1.z;
                x = seb.x + d2.x; pb[2] = (x >= 0.f) ? seb.y * d2.y : seb.z * d2.z;
                x = seb.x + d3.x; pb[3] = (x >= 0.f) ? seb.y * d3.y : seb.z * d3.z;
            }
            pa[0] = ((awa_c >> (jb + 2*q    )) & 1u) ? pa[0] : 0.f;
            pa[1] = ((awa_c >> (jb + 2*q + 1)) & 1u) ? pa[1] : 0.f;
            pa[2] = ((awa_c >> (jb + 2*q + 8)) & 1u) ? pa[2] : 0.f;
            pa[3] = ((awa_c >> (jb + 2*q + 9)) & 1u) ? pa[3] : 0.f;
            pb[0] = ((awb_c >> (jb + 2*q    )) & 1u) ? pb[0] : 0.f;
            pb[1] = ((awb_c >> (jb + 2*q + 1)) & 1u) ? pb[1] : 0.f;
            pb[2] = ((awb_c >> (jb + 2*q + 8)) & 1u) ? pb[2] : 0.f;
            pb[3] = ((awb_c >> (jb + 2*q + 9)) & 1u) ? pb[3] : 0.f;
            Sa += pa[0] + pa[1] + pa[2] + pa[3];
            Sb += pb[0] + pb[1] + pb[2] + pb[3];

            // A fragments: single fp16 (rn)
            u32 a[4];
            PK16(a[0], pa[1], pa[0]);   // row g,   k pair lo
            PK16(a[1], pb[1], pb[0]);   // row g+8, k pair lo
            PK16(a[2], pa[3], pa[2]);   // row g,   k pair hi
            PK16(a[3], pb[3], pb[2]);   // row g+8, k pair hi

            #pragma unroll
            for (int pr = 0; pr < 4; pr++) {
                u32 aoff = (u32)((pr * 16 * BSTRIDE + ks * 16) * 2);
                u32 h0, h1, h2, h3;
                LDMX4(h0, h1, h2, h3, btb + aoff);
                MMA_F16(C[pr * 2],     a, h0, h1);
                MMA_F16(C[pr * 2 + 1], a, h2, h3);
            }
        }
    }

    // reduce S across the quad (j-coverage split over q)
    Sa += __shfl_xor_sync(~0u, Sa, 1); Sa += __shfl_xor_sync(~0u, Sa, 2);
    Sb += __shfl_xor_sync(~0u, Sb, 1); Sb += __shfl_xor_sync(~0u, Sb, 2);
    float inva = 1.0f / Sa, invb = 1.0f / Sb;

    float* oa = out + ((size_t)bh + ia) * FOUT;
    float* ob = out + ((size_t)bh + ib) * FOUT;
    #pragma unroll
    for (int ot = 0; ot < 8; ot++) {
        int col = ot * 8 + 2 * q;
        float2 bv = __ldg((const float2*)(bias + col));
        *(float2*)(oa + col) = make_float2(C[ot][0] * inva + bv.x,
                                           C[ot][1] * inva + bv.y);
        *(float2*)(ob + col) = make_float2(C[ot][2] * invb + bv.x,
                                           C[ot][3] * invb + bv.y);
    }
}

// ---------------------------------------------------------------------------
extern "C" void kernel_launch(void* const* d_in, const int* in_sizes, int n_in,
                              void* d_out, int out_size)
{
    const float* h     = (const float*)d_in[0];
    const int*   adj   = (const int*)  d_in[1];
    const float* w     = (const float*)d_in[2];
    const float* a_src = (const float*)d_in[3];
    const float* a_dst = (const float*)d_in[4];
    const float* bias  = (const float*)d_in[5];
    float* out = (float*)d_out;

    pack_adj_kernel<<<(BS * NN * NN) / 2048, 256>>>(adj);
    hp_kernel<<<dim3(NN / 32, NH, BS), 256>>>(h, w, a_src, a_dst);
    attn_mma_kernel<<<dim3(NN / 128, NH, BS), 256>>>(bias, out);
}

// round 12
// speedup vs baseline: 3.3166x; 1.0093x over previous
#include <cuda_runtime.h>
#include <cuda_fp16.h>
#include <cstdint>

#define BS   16
#define NN   1024
#define FIN  128
#define FOUT 64
#define NH   4
#define NEG  0.2f
#define NW   32          // adj words per row

typedef unsigned int       u32;
typedef unsigned long long u64;

// ---- scratch ----
__device__ __half    g_hpT[(size_t)BS*NH*FOUT*NN];     // 8 MB [bh][o][j] K-major fp16
__device__ unsigned  g_adj[(size_t)BS*NN*NW];          // 2 MB bitmask
__device__ float4    g_sE [BS*NH*NN];   // (src, 2^-k*e^src, 2^-k*e^.2src, -)  k=rint(src*log2e)
__device__ float4    g_dFF[BS*NH*NN];   // (dst, e^dst, e^.2dst, -)

// ---------------------------------------------------------------------------
// Kernel 1: pack adjacency -> bitmask. One warp packs 256 ints (MLP=8).
// ---------------------------------------------------------------------------
__global__ void __launch_bounds__(256) pack_adj_kernel(const int* __restrict__ adj) {
    int warp = (blockIdx.x * blockDim.x + threadIdx.x) >> 5;
    int lane = threadIdx.x & 31;
    size_t base = (size_t)warp * 256;
    int v0 = adj[base +   0 + lane]; int v1 = adj[base +  32 + lane];
    int v2 = adj[base +  64 + lane]; int v3 = adj[base +  96 + lane];
    int v4 = adj[base + 128 + lane]; int v5 = adj[base + 160 + lane];
    int v6 = adj[base + 192 + lane]; int v7 = adj[base + 224 + lane];
    unsigned m0 = __ballot_sync(~0u, v0 != 0), m1 = __ballot_sync(~0u, v1 != 0);
    unsigned m2 = __ballot_sync(~0u, v2 != 0), m3 = __ballot_sync(~0u, v3 != 0);
    unsigned m4 = __ballot_sync(~0u, v4 != 0), m5 = __ballot_sync(~0u, v5 != 0);
    unsigned m6 = __ballot_sync(~0u, v6 != 0), m7 = __ballot_sync(~0u, v7 != 0);
    if (lane == 0) {
        uint4* o = (uint4*)&g_adj[(size_t)warp * 8];
        o[0] = make_uint4(m0, m1, m2, m3);
        o[1] = make_uint4(m4, m5, m6, m7);
    }
}

// ---------------------------------------------------------------------------
// Kernel 2: h_prime GEMM + tanh + src/dst tables; writes TRANSPOSED fp16 hp
// (K-major B operand). src table carries an exact 2^-k row rescale so the
// fp16 P operand never leaves range (cancels in the final numerator/S ratio).
// ---------------------------------------------------------------------------
__global__ void __launch_bounds__(256) hp_kernel(
    const float* __restrict__ h, const float* __restrict__ w,
    const float* __restrict__ a_src, const float* __restrict__ a_dst)
{
    int b = blockIdx.z, hd = blockIdx.y, nt = blockIdx.x;
    __shared__ float w_sh[FIN][FOUT];      // 32 KB
    __shared__ float stage[32][65];        // transpose staging
    __shared__ float as_sh[FOUT], ad_sh[FOUT];

    int t = threadIdx.x;
    for (int idx = t; idx < FIN * FOUT; idx += 256)
        w_sh[idx >> 6][idx & 63] = w[hd * FIN * FOUT + idx];
    if (t < FOUT) { as_sh[t] = a_src[hd * FOUT + t]; ad_sh[t] = a_dst[hd * FOUT + t]; }
    __syncthreads();

    int nl = t >> 3, og = t & 7;
    int n = nt * 32 + nl;
    const float* hrow = h + ((size_t)b * NN + n) * FIN;

    float acc[8] = {0.f,0.f,0.f,0.f,0.f,0.f,0.f,0.f};
    #pragma unroll 8
    for (int f = 0; f < FIN; f++) {
        float hv = __ldg(hrow + f);
        const float4* wr = (const float4*)&w_sh[f][og * 8];
        float4 w0 = wr[0], w1 = wr[1];
        acc[0] += hv * w0.x; acc[1] += hv * w0.y;
        acc[2] += hv * w0.z; acc[3] += hv * w0.w;
        acc[4] += hv * w1.x; acc[5] += hv * w1.y;
        acc[6] += hv * w1.z; acc[7] += hv * w1.w;
    }
    #pragma unroll
    for (int k = 0; k < 8; k++) stage[nl][og * 8 + k] = acc[k];

    float ps = 0.f, pd = 0.f;
    #pragma unroll
    for (int k = 0; k < 8; k++) {
        float tv = tanhf(acc[k]);
        ps += tv * as_sh[og * 8 + k];
        pd += tv * ad_sh[og * 8 + k];
    }
    #pragma unroll
    for (int off = 4; off; off >>= 1) {
        ps += __shfl_down_sync(~0u, ps, off, 8);
        pd += __shfl_down_sync(~0u, pd, off, 8);
    }
    if (og == 0) {
        int idx = (b * NH + hd) * NN + n;
        // exact 2^-k rescale: keeps fp16 P operand in range; cancels in out = num/S
        float kf = rintf(ps * 1.44269504089f);
        float sc = ldexpf(1.0f, -(int)kf);
        g_sE [idx] = make_float4(ps, expf(ps) * sc, expf(NEG * ps) * sc, 0.f);
        g_dFF[idx] = make_float4(pd, expf(pd), expf(NEG * pd), 0.f);
    }
    __syncthreads();

    // transpose + fp16 convert: thread -> (o = t>>2, 8-n chunk c = t&3)
    {
        int o = t >> 2, c = t & 3;
        int bh64 = (b * NH + hd) * FOUT;
        u32 uh[4];
        #pragma unroll
        for (int q = 0; q < 4; q++) {
            float p0 = stage[c * 8 + q * 2][o];
            float p1 = stage[c * 8 + q * 2 + 1][o];
            __half2 hh = __floats2half2_rn(p0, p1);
            uh[q] = *(u32*)&hh;
        }
        size_t off = (size_t)(bh64 + o) * NN + nt * 32 + c * 8;
        *(uint4*)&g_hpT[off] = make_uint4(uh[0], uh[1], uh[2], uh[3]);
    }
}

// ---------------------------------------------------------------------------
// Kernel 3: attention via mma.sync m16n8k16 fp16. P single fp16 (rn, row
// rescaled); hp single fp16. TWO jt tiles (K=64) per pipeline step: 16
// barriers instead of 32, two independent consume chains per window (2x ILP
// between barriers). 3-stage cp.async pipeline (prefetch 2 steps = 4 jt).
// ---------------------------------------------------------------------------
#define BSTRIDE 40                       // fp16 per smem B row (ldmatrix conflict-free)
#define HALFB   (64 * BSTRIDE * 2)       // bytes per single-jt B tile (5120)
#define STEPB   (2 * HALFB)              // bytes per stage (2 jt)

#define MMA_F16(C, A, b0, b1)                                                  \
    asm volatile("mma.sync.aligned.m16n8k16.row.col.f32.f16.f16.f32 "          \
        "{%0,%1,%2,%3}, {%4,%5,%6,%7}, {%8,%9}, {%0,%1,%2,%3};"                \
        : "+f"((C)[0]), "+f"((C)[1]), "+f"((C)[2]), "+f"((C)[3])               \
        : "r"((A)[0]), "r"((A)[1]), "r"((A)[2]), "r"((A)[3]), "r"(b0), "r"(b1))

#define LDMX4(r0, r1, r2, r3, a)                                               \
    asm volatile("ldmatrix.sync.aligned.m8n8.x4.shared.b16 {%0,%1,%2,%3}, [%4];" \
        : "=r"(r0), "=r"(r1), "=r"(r2), "=r"(r3) : "r"(a))

#define CP16(dst, src) \
    asm volatile("cp.async.cg.shared.global [%0], [%1], 16;" :: "r"(dst), "l"(src) : "memory")
#define CP_COMMIT() asm volatile("cp.async.commit_group;" ::: "memory")
#define CP_WAIT1()  asm volatile("cp.async.wait_group 1;" ::: "memory")

// pack two fp32 -> fp16x2 (first src -> HIGH half, matching A-frag k order)
#define PK16(dst, hi, lo) \
    asm("cvt.rn.f16x2.f32 %0, %1, %2;" : "=r"(dst) : "f"(hi), "f"(lo))

__global__ void __launch_bounds__(256, 2) attn_mma_kernel(
    const float* __restrict__ bias, float* __restrict__ out)
{
    __shared__ __align__(16) __half Bt[3][2 * 64 * BSTRIDE];  // 30.7 KB
    __shared__ __align__(16) float4 dffs[3][64];              // 3 KB

    int t = threadIdx.x;
    int lane = t & 31, w = t >> 5;
    int q = lane & 3, g = lane >> 2;
    int b = blockIdx.z, hd = blockIdx.y, it = blockIdx.x;
    int i0 = it * 128;
    int bh = (b * NH + hd) * NN;
    int bh64 = (b * NH + hd) * FOUT;

    int ia = i0 + w * 16 + g;
    int ib = ia + 8;
    float4 sea = g_sE[bh + ia];
    float4 seb = g_sE[bh + ib];
    const unsigned* awa_p = g_adj + (size_t)(b * NN + ia) * NW;
    const unsigned* awb_p = g_adj + (size_t)(b * NN + ib) * NW;

    float Sa = 0.f, Sb = 0.f;
    float C[8][4];
    #pragma unroll
    for (int ot = 0; ot < 8; ot++) {
        C[ot][0] = 0.f; C[ot][1] = 0.f; C[ot][2] = 0.f; C[ot][3] = 0.f;
    }

    // staging: row = o (t>>2), seg = 16B chunk (t&3)
    int srow = t >> 2, sseg = t & 3;
    const uint4* gsrc = (const uint4*)(g_hpT + (size_t)(bh64 + srow) * NN);
    u32 sBt  = (u32)__cvta_generic_to_shared(Bt);
    u32 sDff = (u32)__cvta_generic_to_shared(dffs);
    u32 doff = (u32)(srow * BSTRIDE + sseg * 8) * 2;
    const float4* dsrc = (const float4*)(g_dFF + bh) + t;   // valid when t<64

    // ldmatrix per-lane term: n-row = (l&7)+((l>>4)&1)*8, k-add = ((l>>3)&1)*8
    u32 lmterm = (u32)((((lane & 7) + ((lane >> 4) & 1) * 8) * BSTRIDE
                        + ((lane >> 3) & 1) * 8) * 2);

    // one stage = two jt tiles (K=64)
    #define ISSUE_STAGE(s, step) do {                                          \
        int _j0 = 2 * (step);                                                  \
        CP16(sBt + (u32)(s) * STEPB + doff,         gsrc + _j0 * 4 + sseg);    \
        CP16(sBt + (u32)(s) * STEPB + HALFB + doff, gsrc + (_j0 + 1) * 4 + sseg); \
        if (t < 64) CP16(sDff + (u32)(s) * 1024 + (u32)t * 16, dsrc + (step) * 64); \
    } while (0)

    ISSUE_STAGE(0, 0); CP_COMMIT();
    ISSUE_STAGE(1, 1); CP_COMMIT();

    unsigned awa0 = __ldg(awa_p),     awb0 = __ldg(awb_p);
    unsigned awa1 = __ldg(awa_p + 1), awb1 = __ldg(awb_p + 1);

    for (int m = 0; m < 16; m++) {
        int s = m % 3;
        // pending groups here: {g_m, g_m+1}; wait_group 1 => stage s complete
        CP_WAIT1();
        __syncthreads();   // ALL threads done with stage (m-1)%3 => safe to overwrite
        if (m < 14) { int sn = (m + 2) % 3; ISSUE_STAGE(sn, m + 2); }
        CP_COMMIT();

        unsigned awc[2][2] = {{awa0, awb0}, {awa1, awb1}};
        int nm = (m < 15) ? m + 1 : 15;
        awa0 = __ldg(awa_p + 2 * nm);     awb0 = __ldg(awb_p + 2 * nm);
        awa1 = __ldg(awa_p + 2 * nm + 1); awb1 = __ldg(awb_p + 2 * nm + 1);

        #pragma unroll
        for (int hh = 0; hh < 2; hh++) {
            unsigned awa_c = awc[hh][0], awb_c = awc[hh][1];
            u32 btb = sBt + (u32)s * STEPB + (u32)hh * HALFB + lmterm;
            const float4* dfp = &dffs[s][hh * 32];

            #pragma unroll
            for (int ks = 0; ks < 2; ks++) {
                int jb = ks * 16;
                float4 d0 = dfp[jb + 2 * q];
                float4 d1 = dfp[jb + 2 * q + 1];
                float4 d2 = dfp[jb + 2 * q + 8];
                float4 d3 = dfp[jb + 2 * q + 9];

                float pa[4], pb[4];
                {
                    float x;
                    x = sea.x + d0.x; pa[0] = (x >= 0.f) ? sea.y * d0.y : sea.z * d0.z;
                    x = sea.x + d1.x; pa[1] = (x >= 0.f) ? sea.y * d1.y : sea.z * d1.z;
                    x = sea.x + d2.x; pa[2] = (x >= 0.f) ? sea.y * d2.y : sea.z * d2.z;
                    x = sea.x + d3.x; pa[3] = (x >= 0.f) ? sea.y * d3.y : sea.z * d3.z;
                    x = seb.x + d0.x; pb[0] = (x >= 0.f) ? seb.y * d0.y : seb.z * d0.z;
                    x = seb.x + d1.x; pb[1] = (x >= 0.f) ? seb.y * d1.y : seb.z * d1.z;
                    x = seb.x + d2.x; pb[2] = (x >= 0.f) ? seb.y * d2.y : seb.z * d2.z;
                    x = seb.x + d3.x; pb[3] = (x >= 0.f) ? seb.y * d3.y : seb.z * d3.z;
                }
                pa[0] = ((awa_c >> (jb + 2*q    )) & 1u) ? pa[0] : 0.f;
                pa[1] = ((awa_c >> (jb + 2*q + 1)) & 1u) ? pa[1] : 0.f;
                pa[2] = ((awa_c >> (jb + 2*q + 8)) & 1u) ? pa[2] : 0.f;
                pa[3] = ((awa_c >> (jb + 2*q + 9)) & 1u) ? pa[3] : 0.f;
                pb[0] = ((awb_c >> (jb + 2*q    )) & 1u) ? pb[0] : 0.f;
                pb[1] = ((awb_c >> (jb + 2*q + 1)) & 1u) ? pb[1] : 0.f;
                pb[2] = ((awb_c >> (jb + 2*q + 8)) & 1u) ? pb[2] : 0.f;
                pb[3] = ((awb_c >> (jb + 2*q + 9)) & 1u) ? pb[3] : 0.f;
                Sa += pa[0] + pa[1] + pa[2] + pa[3];
                Sb += pb[0] + pb[1] + pb[2] + pb[3];

                // A fragments: single fp16 (rn)
                u32 a[4];
                PK16(a[0], pa[1], pa[0]);   // row g,   k pair lo
                PK16(a[1], pb[1], pb[0]);   // row g+8, k pair lo
                PK16(a[2], pa[3], pa[2]);   // row g,   k pair hi
                PK16(a[3], pb[3], pb[2]);   // row g+8, k pair hi

                #pragma unroll
                for (int pr = 0; pr < 4; pr++) {
                    u32 aoff = (u32)((pr * 16 * BSTRIDE + ks * 16) * 2);
                    u32 h0, h1, h2, h3;
                    LDMX4(h0, h1, h2, h3, btb + aoff);
                    MMA_F16(C[pr * 2],     a, h0, h1);
                    MMA_F16(C[pr * 2 + 1], a, h2, h3);
                }
            }
        }
    }

    // reduce S across the quad (j-coverage split over q)
    Sa += __shfl_xor_sync(~0u, Sa, 1); Sa += __shfl_xor_sync(~0u, Sa, 2);
    Sb += __shfl_xor_sync(~0u, Sb, 1); Sb += __shfl_xor_sync(~0u, Sb, 2);
    float inva = 1.0f / Sa, invb = 1.0f / Sb;

    float* oa = out + ((size_t)bh + ia) * FOUT;
    float* ob = out + ((size_t)bh + ib) * FOUT;
    #pragma unroll
    for (int ot = 0; ot < 8; ot++) {
        int col = ot * 8 + 2 * q;
        float2 bv = __ldg((const float2*)(bias + col));
        *(float2*)(oa + col) = make_float2(C[ot][0] * inva + bv.x,
                                           C[ot][1] * inva + bv.y);
        *(float2*)(ob + col) = make_float2(C[ot][2] * invb + bv.x,
                                           C[ot][3] * invb + bv.y);
    }
}

// ---------------------------------------------------------------------------
extern "C" void kernel_launch(void* const* d_in, const int* in_sizes, int n_in,
                              void* d_out, int out_size)
{
    const float* h     = (const float*)d_in[0];
    const int*   adj   = (const int*)  d_in[1];
    const float* w     = (const float*)d_in[2];
    const float* a_src = (const float*)d_in[3];
    const float* a_dst = (const float*)d_in[4];
    const float* bias  = (const float*)d_in[5];
    float* out = (float*)d_out;

    pack_adj_kernel<<<(BS * NN * NN) / 2048, 256>>>(adj);
    hp_kernel<<<dim3(NN / 32, NH, BS), 256>>>(h, w, a_src, a_dst);
    attn_mma_kernel<<<dim3(NN / 128, NH, BS), 256>>>(bias, out);
}